// round 3
// baseline (speedup 1.0000x reference)
#include <cuda_runtime.h>
#include <cstdint>

// HypercomplexLinear via DFT-4 diagonalization, fully fused:
//   out_k = sum_j x_j @ W_{(k-j)%4}^T + bias
// DFT4: a0=X0@W0'^T/4, a2=X2@W2'^T/4, P=(Xr@Wr^T - Xs@Ws^T)/2, Q=(Xr@Ws^T + Xs@Wr^T)/2
//   out_0=a0+a2+P, out_1=a0-a2+Q, out_2=a0+a2-P, out_3=a0-a2-Q   (scales folded into W)
// One GEMM kernel computes a0,a2,P,Q per (128 x 64-o) tile and writes all 4 outputs.

#define M_DIM 6272
#define KX    768

// k-permutation within 8-groups so fragment pairs (k, k+4) are adjacent:
//   storage col s holds logical k = (s&1)*4 + ((s&7)>>1);  perm(k) = (k&3)*2 + (k>>2)
__device__ float g_Xt[M_DIM * KX];       // [X0|X2|Xr|Xs], tf32, k-permuted
// Prepacked weights, N-major [n][k(perm)] per chunk:
//  per o-tile t (12): chunks 0..5: W0'^T/4 [64n][32k]; 6..11: W2'^T/4 [64n][32k];
//  12..23: WC'/2 [128n][32k], n = [P(0:32),Q(0:32),P(32:64),Q(32:64)] of o-tile
#define BP_TILE 73728                     // words per o-tile: 12*2048 + 12*4096
__device__ float g_Bp[12 * BP_TILE];

__device__ __forceinline__ float f2tf32(float x) {
    uint32_t u; asm("cvt.rna.tf32.f32 %0, %1;" : "=r"(u) : "f"(x));
    return __uint_as_float(u);
}

// ---------------------------------------------------------------------------
// Prep 1: X DFT + tf32 + k-permute. Thread handles 8 consecutive c per row.
// ---------------------------------------------------------------------------
__global__ void prep_xt_kernel(const float* __restrict__ x) {
    int idx = blockIdx.x * blockDim.x + threadIdx.x;   // 6272*24
    int b   = idx / 24;
    int c8  = (idx - b * 24) * 8;
    const float* xb = x + (size_t)b * KX;
    float v[4][8];
#pragma unroll
    for (int j = 0; j < 4; j++) {
        float4 u0 = *reinterpret_cast<const float4*>(xb + j * 192 + c8);
        float4 u1 = *reinterpret_cast<const float4*>(xb + j * 192 + c8 + 4);
        v[j][0]=u0.x; v[j][1]=u0.y; v[j][2]=u0.z; v[j][3]=u0.w;
        v[j][4]=u1.x; v[j][5]=u1.y; v[j][6]=u1.z; v[j][7]=u1.w;
    }
    float comp[4][8];
#pragma unroll
    for (int k = 0; k < 8; k++) {
        float e = v[0][k] + v[2][k], o = v[1][k] + v[3][k];
        comp[0][k] = f2tf32(e + o);            // X0
        comp[1][k] = f2tf32(e - o);            // X2
        comp[2][k] = f2tf32(v[0][k] - v[2][k]); // Xr
        comp[3][k] = f2tf32(v[1][k] - v[3][k]); // Xs
    }
    float* yb = g_Xt + (size_t)b * KX;
#pragma unroll
    for (int cmp = 0; cmp < 4; cmp++) {
        // permuted interleave: stored order = k0,k4,k1,k5,k2,k6,k3,k7
        float4 o0 = make_float4(comp[cmp][0], comp[cmp][4], comp[cmp][1], comp[cmp][5]);
        float4 o1 = make_float4(comp[cmp][2], comp[cmp][6], comp[cmp][3], comp[cmp][7]);
        *reinterpret_cast<float4*>(yb + cmp * 192 + c8)     = o0;
        *reinterpret_cast<float4*>(yb + cmp * 192 + c8 + 4) = o1;
    }
}

// ---------------------------------------------------------------------------
// Prep 2: pack weights. One thread per (t, chunk, n): writes 32 k-words.
// ---------------------------------------------------------------------------
__global__ void prep_bp_kernel(const float* __restrict__ w) {
    int idx = blockIdx.x * blockDim.x + threadIdx.x;   // 12 * 2304
    int t  = idx / 2304;
    int r  = idx - t * 2304;
    int c, n;
    if (r < 768) { c = r >> 6; n = r & 63; }
    else         { int rr = r - 768; c = 12 + (rr >> 7); n = rr & 127; }

    float buf[32];
#pragma unroll
    for (int s = 0; s < 32; s++) {
        int kg = (s & ~7) + ((s & 1) * 4 + ((s & 7) >> 1));  // logical k in chunk
        float val;
        if (c < 6) {
            int cc = c * 32 + kg;
            int o  = t * 64 + n;
            val = 0.25f * (w[o*192+cc] + w[147456 + o*192+cc]
                         + w[294912 + o*192+cc] + w[442368 + o*192+cc]);
        } else if (c < 12) {
            int cc = (c - 6) * 32 + kg;
            int o  = t * 64 + n;
            val = 0.25f * (w[o*192+cc] - w[147456 + o*192+cc]
                         + w[294912 + o*192+cc] - w[442368 + o*192+cc]);
        } else {
            int kk = (c - 12) * 32 + kg;           // 0..383
            int pq = (n >> 5) & 1;                 // 0=P, 1=Q
            int o  = t * 64 + (n >> 6) * 32 + (n & 31);
            if (kk < 192) {        // Xr rows
                int cc = kk;
                val = pq ? 0.5f * (w[147456 + o*192+cc] - w[442368 + o*192+cc])   // Ws
                         : 0.5f * (w[o*192+cc] - w[294912 + o*192+cc]);           // Wr
            } else {               // Xs rows
                int cc = kk - 192;
                val = pq ? 0.5f * (w[o*192+cc] - w[294912 + o*192+cc])            // Wr
                         : -0.5f * (w[147456 + o*192+cc] - w[442368 + o*192+cc]); // -Ws
            }
        }
        buf[s] = f2tf32(val);
    }
    float* dst = g_Bp + (size_t)t * BP_TILE
               + (c < 12 ? c * 2048 : 24576 + (c - 12) * 4096) + n * 32;
#pragma unroll
    for (int s = 0; s < 8; s++)
        reinterpret_cast<float4*>(dst)[s] =
            make_float4(buf[4*s], buf[4*s+1], buf[4*s+2], buf[4*s+3]);
}

// ---------------------------------------------------------------------------
// Fused GEMM. Grid (12 o-tiles, 49 m-tiles), 256 threads.
// Smem per stage: A [128][32] + B [128][32] words (XOR-8 swizzled), 32KB.
// ---------------------------------------------------------------------------
#define STAGES 3
#define STG_W 8192
#define SMEM_BYTES (STAGES * STG_W * 4)

__device__ __forceinline__ void mma_tf32(float* c, uint32_t a0, uint32_t a1,
                                         uint32_t a2, uint32_t a3,
                                         uint32_t b0, uint32_t b1) {
    asm volatile(
        "mma.sync.aligned.m16n8k8.row.col.f32.tf32.tf32.f32 "
        "{%0,%1,%2,%3}, {%4,%5,%6,%7}, {%8,%9}, {%0,%1,%2,%3};"
        : "+f"(c[0]), "+f"(c[1]), "+f"(c[2]), "+f"(c[3])
        : "r"(a0), "r"(a1), "r"(a2), "r"(a3), "r"(b0), "r"(b1));
}

__global__ __launch_bounds__(256, 1)
void gemm_fused_kernel(const float* __restrict__ bias, float* __restrict__ out) {
    extern __shared__ float sm[];
    const int t   = blockIdx.x;          // o-tile
    const int bm  = blockIdx.y * 128;
    const int tid  = threadIdx.x;
    const int warp = tid >> 5;
    const int lane = tid & 31;
    const int g    = lane >> 2;
    const int tig  = lane & 3;
    const int wm   = (warp >> 1) * 32;   // 4 warps over M
    const int wn2  = (warp & 1) * 32;    // half-phase N offset (64-wide)
    const int wn3  = (warp & 1) * 64;    // full-phase N offset (128-wide)

    float accA0[2][4][4], accA1[2][4][4], accB[2][8][4];
#pragma unroll
    for (int mi = 0; mi < 2; mi++) {
#pragma unroll
        for (int ni = 0; ni < 4; ni++)
#pragma unroll
            for (int r = 0; r < 4; r++) { accA0[mi][ni][r] = 0.f; accA1[mi][ni][r] = 0.f; }
#pragma unroll
        for (int ni = 0; ni < 8; ni++)
#pragma unroll
            for (int r = 0; r < 4; r++) accB[mi][ni][r] = 0.f;
    }

    // loader mapping
    const int arow = tid >> 3;              // 0..31
    const int acw  = (tid & 7) << 2;        // word col 0,4..28
    const int aswz = (arow & 3) << 3;
    const float* gA = g_Xt + (size_t)(bm + arow) * KX + acw;
    const float* gB = g_Bp + (size_t)t * BP_TILE;
    const uint32_t smem_base = (uint32_t)__cvta_generic_to_shared(sm);

    auto load_chunk = [&](int c, int s) {
        uint32_t ab = smem_base + (uint32_t)(s * STG_W) * 4u;
#pragma unroll
        for (int i = 0; i < 4; i++) {
            uint32_t d = ab + (uint32_t)((arow + i * 32) * 32 + (acw ^ aswz)) * 4u;
            const float* p = gA + (size_t)(i * 32) * KX + c * 32;
            asm volatile("cp.async.cg.shared.global [%0], [%1], 16;\n" :: "r"(d), "l"(p));
        }
        uint32_t bb = ab + 4096u * 4u;
        const float* pb = gB + (c < 12 ? c * 2048 : 24576 + (c - 12) * 4096);
#pragma unroll
        for (int i = 0; i < 2; i++) {
            int n = arow + i * 32;
            uint32_t d = bb + (uint32_t)(n * 32 + (acw ^ aswz)) * 4u;
            asm volatile("cp.async.cg.shared.global [%0], [%1], 16;\n"
                         :: "r"(d), "l"(pb + n * 32 + acw));
        }
        if (c >= 12) {
#pragma unroll
            for (int i = 2; i < 4; i++) {
                int n = arow + i * 32;
                uint32_t d = bb + (uint32_t)(n * 32 + (acw ^ aswz)) * 4u;
                asm volatile("cp.async.cg.shared.global [%0], [%1], 16;\n"
                             :: "r"(d), "l"(pb + n * 32 + acw));
            }
        }
    };

    const int fswz = (g & 3) << 3;   // fragment-read XOR

    auto compute_half = [&](int s, float (&acc)[2][4][4]) {
        const float* As = sm + s * STG_W;
        const float* Bs = As + 4096;
#pragma unroll
        for (int ks = 0; ks < 32; ks += 8) {
            int kc = (ks + 2 * tig) ^ fswz;
            float2 a[2][2];
#pragma unroll
            for (int mi = 0; mi < 2; mi++) {
                int row = wm + mi * 16 + g;
                a[mi][0] = *reinterpret_cast<const float2*>(As + row * 32 + kc);
                a[mi][1] = *reinterpret_cast<const float2*>(As + (row + 8) * 32 + kc);
            }
#pragma unroll
            for (int ni = 0; ni < 4; ni++) {
                int col = wn2 + ni * 8 + g;
                float2 b = *reinterpret_cast<const float2*>(Bs + col * 32 + kc);
#pragma unroll
                for (int mi = 0; mi < 2; mi++)
                    mma_tf32(acc[mi][ni],
                             __float_as_uint(a[mi][0].x), __float_as_uint(a[mi][1].x),
                             __float_as_uint(a[mi][0].y), __float_as_uint(a[mi][1].y),
                             __float_as_uint(b.x), __float_as_uint(b.y));
            }
        }
    };
    auto compute_full = [&](int s) {
        const float* As = sm + s * STG_W;
        const float* Bs = As + 4096;
#pragma unroll
        for (int ks = 0; ks < 32; ks += 8) {
            int kc = (ks + 2 * tig) ^ fswz;
            float2 a[2][2];
#pragma unroll
            for (int mi = 0; mi < 2; mi++) {
                int row = wm + mi * 16 + g;
                a[mi][0] = *reinterpret_cast<const float2*>(As + row * 32 + kc);
                a[mi][1] = *reinterpret_cast<const float2*>(As + (row + 8) * 32 + kc);
            }
#pragma unroll
            for (int ni = 0; ni < 8; ni++) {
                int col = wn3 + ni * 8 + g;
                float2 b = *reinterpret_cast<const float2*>(Bs + col * 32 + kc);
#pragma unroll
                for (int mi = 0; mi < 2; mi++)
                    mma_tf32(accB[mi][ni],
                             __float_as_uint(a[mi][0].x), __float_as_uint(a[mi][1].x),
                             __float_as_uint(a[mi][0].y), __float_as_uint(a[mi][1].y),
                             __float_as_uint(b.x), __float_as_uint(b.y));
            }
        }
    };

    int fetch = 0;
#pragma unroll
    for (int s = 0; s < STAGES - 1; s++) {
        load_chunk(fetch, s);
        asm volatile("cp.async.commit_group;\n");
        fetch++;
    }
    asm volatile("cp.async.wait_group %0;\n" :: "n"(STAGES - 2));
    __syncthreads();

    for (int c = 0; c < 24; c++) {
        if (fetch < 24) load_chunk(fetch, fetch % STAGES);
        asm volatile("cp.async.commit_group;\n");
        fetch++;

        int s = c % STAGES;
        if (c < 6)       compute_half(s, accA0);
        else if (c < 12) compute_half(s, accA1);
        else             compute_full(s);

        asm volatile("cp.async.wait_group %0;\n" :: "n"(STAGES - 2));
        __syncthreads();
    }

    // Fused combine epilogue: out_k from a0,a2,P,Q + bias, direct to out.
    const int o_base = t * 64 + wn2;
#pragma unroll
    for (int ni = 0; ni < 4; ni++) {
        int o = o_base + ni * 8 + 2 * tig;
        float2 bv0 = *reinterpret_cast<const float2*>(bias + o);
        float2 bv1 = *reinterpret_cast<const float2*>(bias + 768 + o);
        float2 bv2 = *reinterpret_cast<const float2*>(bias + 1536 + o);
        float2 bv3 = *reinterpret_cast<const float2*>(bias + 2304 + o);
#pragma unroll
        for (int mi = 0; mi < 2; mi++) {
            int row = bm + wm + mi * 16 + g;
#pragma unroll
            for (int h = 0; h < 2; h++) {           // h=0: rows row, h=1: row+8
                float a0x = accA0[mi][ni][2*h],   a0y = accA0[mi][ni][2*h+1];
                float a2x = accA1[mi][ni][2*h],   a2y = accA1[mi][ni][2*h+1];
                float px  = accB[mi][ni][2*h],    py  = accB[mi][ni][2*h+1];
                float qx  = accB[mi][ni+4][2*h],  qy  = accB[mi][ni+4][2*h+1];
                float sx = a0x + a2x, sy = a0y + a2y;
                float dx = a0x - a2x, dy = a0y - a2y;
                float* ob = out + (size_t)(row + 8 * h) * 3072;
                *reinterpret_cast<float2*>(ob + o)        = make_float2(sx + px + bv0.x, sy + py + bv0.y);
                *reinterpret_cast<float2*>(ob + 768 + o)  = make_float2(dx + qx + bv1.x, dy + qy + bv1.y);
                *reinterpret_cast<float2*>(ob + 1536 + o) = make_float2(sx - px + bv2.x, sy - py + bv2.y);
                *reinterpret_cast<float2*>(ob + 2304 + o) = make_float2(dx - qx + bv3.x, dy - qy + bv3.y);
            }
        }
    }
}

// ---------------------------------------------------------------------------
extern "C" void kernel_launch(void* const* d_in, const int* in_sizes, int n_in,
                              void* d_out, int out_size) {
    const float* x    = (const float*)d_in[0];
    const float* w    = (const float*)d_in[1];
    const float* bias = (const float*)d_in[2];
    float* out = (float*)d_out;

    cudaFuncSetAttribute(gemm_fused_kernel,
                         cudaFuncAttributeMaxDynamicSharedMemorySize, SMEM_BYTES);

    prep_xt_kernel<<<(M_DIM * 24) / 256, 256>>>(x);     // 588 blocks
    prep_bp_kernel<<<(12 * 2304) / 256, 256>>>(w);      // 108 blocks

    dim3 grid(12, 49);
    gemm_fused_kernel<<<grid, 256, SMEM_BYTES>>>(bias, out);
}

// round 4
// speedup vs baseline: 1.0479x; 1.0479x over previous
#include <cuda_runtime.h>
#include <cstdint>

// HypercomplexLinear via DFT-4 diagonalization, fused GEMM+combine.
//   a0 = X0@W0'^T/4 (K=192), a2 = X2@W2'^T/4 (K=192),
//   [P|Q] = [Xr|Xs]@WC/2     (K=384)
//   out_0=a0+a2+P, out_1=a0-a2+Q, out_2=a0+a2-P, out_3=a0-a2-Q  (+bias)
// CTA tile: 128 M x 32 o (computes a0,a2 32-wide and P,Q 32-wide each).

#define M_DIM 6272
#define KX    768

// k-permutation within 8-groups: storage slot s holds logical k=(s&1)*4+((s&7)>>1)
__device__ float g_Xt[M_DIM * KX];          // [X0|X2|Xr|Xs], tf32, k-permuted
// Per o-tile t (24 tiles of 32 o): [a0: 6 chunks 32nx32k | a2: 6 | PQ: 12 chunks 64nx32k]
// PQ n-layout: [P(0:16) | Q(0:16) | P(16:32) | Q(16:32)]
#define BP_TILE 36864
__device__ float g_Bp[24 * BP_TILE];

__device__ __forceinline__ float f2tf32(float x) {
    uint32_t u; asm("cvt.rna.tf32.f32 %0, %1;" : "=r"(u) : "f"(x));
    return __uint_as_float(u);
}

// ---------------------------------------------------------------------------
// Prep 1: X DFT + tf32 + k-permute. One thread per 8 c-positions per row.
// ---------------------------------------------------------------------------
__global__ void prep_xt_kernel(const float* __restrict__ x) {
    int idx = blockIdx.x * blockDim.x + threadIdx.x;   // 6272*24
    int b   = idx / 24;
    int c8  = (idx - b * 24) * 8;
    const float* xb = x + (size_t)b * KX;
    float v[4][8];
#pragma unroll
    for (int j = 0; j < 4; j++) {
        float4 u0 = *reinterpret_cast<const float4*>(xb + j * 192 + c8);
        float4 u1 = *reinterpret_cast<const float4*>(xb + j * 192 + c8 + 4);
        v[j][0]=u0.x; v[j][1]=u0.y; v[j][2]=u0.z; v[j][3]=u0.w;
        v[j][4]=u1.x; v[j][5]=u1.y; v[j][6]=u1.z; v[j][7]=u1.w;
    }
    float comp[4][8];
#pragma unroll
    for (int k = 0; k < 8; k++) {
        float e = v[0][k] + v[2][k], o = v[1][k] + v[3][k];
        comp[0][k] = f2tf32(e + o);
        comp[1][k] = f2tf32(e - o);
        comp[2][k] = f2tf32(v[0][k] - v[2][k]);
        comp[3][k] = f2tf32(v[1][k] - v[3][k]);
    }
    float* yb = g_Xt + (size_t)b * KX;
#pragma unroll
    for (int cmp = 0; cmp < 4; cmp++) {
        float4 o0 = make_float4(comp[cmp][0], comp[cmp][4], comp[cmp][1], comp[cmp][5]);
        float4 o1 = make_float4(comp[cmp][2], comp[cmp][6], comp[cmp][3], comp[cmp][7]);
        *reinterpret_cast<float4*>(yb + cmp * 192 + c8)     = o0;
        *reinterpret_cast<float4*>(yb + cmp * 192 + c8 + 4) = o1;
    }
}

// ---------------------------------------------------------------------------
// Prep 2: pack weights per 32-o tile. One thread per (t, chunk, n) -> 32 words.
// ---------------------------------------------------------------------------
__global__ void prep_bp_kernel(const float* __restrict__ w) {
    int idx = blockIdx.x * blockDim.x + threadIdx.x;   // 24 * 1152
    int t  = idx / 1152;
    int r  = idx - t * 1152;
    int c, n;
    if (r < 384) { c = r >> 5; n = r & 31; }
    else         { int rr = r - 384; c = 12 + (rr >> 6); n = rr & 63; }

    float buf[32];
#pragma unroll
    for (int s = 0; s < 32; s++) {
        int kg = (s & ~7) + ((s & 1) * 4 + ((s & 7) >> 1));  // logical k in chunk
        float val;
        if (c < 6) {
            int cc = c * 32 + kg;
            int o  = t * 32 + n;
            val = 0.25f * (w[o*192+cc] + w[147456 + o*192+cc]
                         + w[294912 + o*192+cc] + w[442368 + o*192+cc]);
        } else if (c < 12) {
            int cc = (c - 6) * 32 + kg;
            int o  = t * 32 + n;
            val = 0.25f * (w[o*192+cc] - w[147456 + o*192+cc]
                         + w[294912 + o*192+cc] - w[442368 + o*192+cc]);
        } else {
            int kk  = (c - 12) * 32 + kg;            // 0..383
            int grp = n >> 4;                        // 0:P-lo 1:Q-lo 2:P-hi 3:Q-hi
            int pq  = grp & 1;
            int o   = t * 32 + (grp >> 1) * 16 + (n & 15);
            if (kk < 192) {      // Xr rows: P->Wr, Q->Ws
                int cc = kk;
                val = pq ? 0.5f * (w[147456 + o*192+cc] - w[442368 + o*192+cc])
                         : 0.5f * (w[o*192+cc] - w[294912 + o*192+cc]);
            } else {             // Xs rows: P->-Ws, Q->Wr
                int cc = kk - 192;
                val = pq ? 0.5f * (w[o*192+cc] - w[294912 + o*192+cc])
                         : -0.5f * (w[147456 + o*192+cc] - w[442368 + o*192+cc]);
            }
        }
        buf[s] = f2tf32(val);
    }
    float* dst = g_Bp + (size_t)t * BP_TILE
               + (c < 12 ? c * 1024 : 12288 + (c - 12) * 2048) + n * 32;
#pragma unroll
    for (int s = 0; s < 8; s++)
        reinterpret_cast<float4*>(dst)[s] =
            make_float4(buf[4*s], buf[4*s+1], buf[4*s+2], buf[4*s+3]);
}

// ---------------------------------------------------------------------------
// Fused GEMM. Grid (24 o-tiles, 49 m-tiles), 256 threads, 2 CTAs/SM.
// Stage: A[128][32] + B[64][32] words, XOR-8 swizzled. 4 stages = 96KB.
// ---------------------------------------------------------------------------
#define STAGES 4
#define STG_W 6144
#define SMEM_BYTES (STAGES * STG_W * 4)

__device__ __forceinline__ void mma_tf32(float* c, uint32_t a0, uint32_t a1,
                                         uint32_t a2, uint32_t a3,
                                         uint32_t b0, uint32_t b1) {
    asm volatile(
        "mma.sync.aligned.m16n8k8.row.col.f32.tf32.tf32.f32 "
        "{%0,%1,%2,%3}, {%4,%5,%6,%7}, {%8,%9}, {%0,%1,%2,%3};"
        : "+f"(c[0]), "+f"(c[1]), "+f"(c[2]), "+f"(c[3])
        : "r"(a0), "r"(a1), "r"(a2), "r"(a3), "r"(b0), "r"(b1));
}

__global__ __launch_bounds__(256, 2)
void gemm_fused_kernel(const float* __restrict__ bias, float* __restrict__ out) {
    extern __shared__ float sm[];
    const int t    = blockIdx.x;
    const int bm   = blockIdx.y * 128;
    const int tid  = threadIdx.x;
    const int warp = tid >> 5;
    const int lane = tid & 31;
    const int g    = lane >> 2;
    const int tig  = lane & 3;
    const int wm   = (warp >> 1) * 32;   // 4 warps over M
    const int wn   = warp & 1;           // 2 warps over o (16 each)

    float accA0[2][2][4], accA1[2][2][4], accPQ[2][4][4];
#pragma unroll
    for (int mi = 0; mi < 2; mi++) {
#pragma unroll
        for (int ni = 0; ni < 2; ni++)
#pragma unroll
            for (int r = 0; r < 4; r++) { accA0[mi][ni][r] = 0.f; accA1[mi][ni][r] = 0.f; }
#pragma unroll
        for (int ni = 0; ni < 4; ni++)
#pragma unroll
            for (int r = 0; r < 4; r++) accPQ[mi][ni][r] = 0.f;
    }

    const int arow = tid >> 3;              // 0..31
    const int acw  = (tid & 7) << 2;        // 0,4,..,28
    const int aswz = (arow & 3) << 3;
    const int acs  = acw ^ aswz;
    const float* gA = g_Xt + (size_t)(bm + arow) * KX + acw;
    const float* gB = g_Bp + (size_t)t * BP_TILE + arow * 32 + acw;
    const uint32_t smem_base = (uint32_t)__cvta_generic_to_shared(sm);

    auto load_chunk = [&](int c, int s) {
        uint32_t ab = smem_base + (uint32_t)(s * STG_W) * 4u;
#pragma unroll
        for (int i = 0; i < 4; i++) {
            uint32_t d = ab + (uint32_t)((arow + i * 32) * 32 + acs) * 4u;
            const float* p = gA + (size_t)(i * 32) * KX + c * 32;
            asm volatile("cp.async.cg.shared.global [%0], [%1], 16;\n" :: "r"(d), "l"(p));
        }
        uint32_t bb = ab + 4096u * 4u;
        const float* pb = gB + (c < 12 ? c * 1024 : 12288 + (c - 12) * 2048);
        {
            uint32_t d = bb + (uint32_t)(arow * 32 + acs) * 4u;
            asm volatile("cp.async.cg.shared.global [%0], [%1], 16;\n" :: "r"(d), "l"(pb));
        }
        if (c >= 12) {
            uint32_t d = bb + (uint32_t)((arow + 32) * 32 + acs) * 4u;
            asm volatile("cp.async.cg.shared.global [%0], [%1], 16;\n"
                         :: "r"(d), "l"(pb + 32 * 32));
        }
    };

    const int fswz = (g & 3) << 3;

    auto compute_half = [&](int s, float (&acc)[2][2][4]) {
        const float* As = sm + s * STG_W;
        const float* Bs = As + 4096;
#pragma unroll
        for (int ks = 0; ks < 32; ks += 8) {
            int kc = (ks + 2 * tig) ^ fswz;
            float2 a[2][2];
#pragma unroll
            for (int mi = 0; mi < 2; mi++) {
                int row = wm + mi * 16 + g;
                a[mi][0] = *reinterpret_cast<const float2*>(As + row * 32 + kc);
                a[mi][1] = *reinterpret_cast<const float2*>(As + (row + 8) * 32 + kc);
            }
#pragma unroll
            for (int ni = 0; ni < 2; ni++) {
                int col = wn * 16 + ni * 8 + g;
                float2 b = *reinterpret_cast<const float2*>(Bs + col * 32 + kc);
#pragma unroll
                for (int mi = 0; mi < 2; mi++)
                    mma_tf32(acc[mi][ni],
                             __float_as_uint(a[mi][0].x), __float_as_uint(a[mi][1].x),
                             __float_as_uint(a[mi][0].y), __float_as_uint(a[mi][1].y),
                             __float_as_uint(b.x), __float_as_uint(b.y));
            }
        }
    };
    auto compute_pq = [&](int s) {
        const float* As = sm + s * STG_W;
        const float* Bs = As + 4096;
#pragma unroll
        for (int ks = 0; ks < 32; ks += 8) {
            int kc = (ks + 2 * tig) ^ fswz;
            float2 a[2][2];
#pragma unroll
            for (int mi = 0; mi < 2; mi++) {
                int row = wm + mi * 16 + g;
                a[mi][0] = *reinterpret_cast<const float2*>(As + row * 32 + kc);
                a[mi][1] = *reinterpret_cast<const float2*>(As + (row + 8) * 32 + kc);
            }
#pragma unroll
            for (int ni = 0; ni < 4; ni++) {
                int col = wn * 32 + ni * 8 + g;
                float2 b = *reinterpret_cast<const float2*>(Bs + col * 32 + kc);
#pragma unroll
                for (int mi = 0; mi < 2; mi++)
                    mma_tf32(accPQ[mi][ni],
                             __float_as_uint(a[mi][0].x), __float_as_uint(a[mi][1].x),
                             __float_as_uint(a[mi][0].y), __float_as_uint(a[mi][1].y),
                             __float_as_uint(b.x), __float_as_uint(b.y));
            }
        }
    };

    int fetch = 0;
#pragma unroll
    for (int s = 0; s < STAGES - 1; s++) {
        load_chunk(fetch, fetch);
        asm volatile("cp.async.commit_group;\n");
        fetch++;
    }
    asm volatile("cp.async.wait_group %0;\n" :: "n"(STAGES - 2));
    __syncthreads();

    auto step_tail = [&]() {
        asm volatile("cp.async.commit_group;\n");
        asm volatile("cp.async.wait_group %0;\n" :: "n"(STAGES - 2));
    };

    for (int c = 0; c < 6; c++) {
        if (fetch < 24) load_chunk(fetch, fetch & 3);
        fetch++;
        compute_half(c & 3, accA0);
        step_tail();
        __syncthreads();
    }
    for (int c = 6; c < 12; c++) {
        if (fetch < 24) load_chunk(fetch, fetch & 3);
        fetch++;
        compute_half(c & 3, accA1);
        step_tail();
        __syncthreads();
    }
    for (int c = 12; c < 24; c++) {
        if (fetch < 24) load_chunk(fetch, fetch & 3);
        fetch++;
        compute_pq(c & 3);
        step_tail();
        __syncthreads();
    }

    // Fused combine epilogue
    const int o0 = t * 32 + wn * 16;
#pragma unroll
    for (int ni = 0; ni < 2; ni++) {
        int o = o0 + ni * 8 + 2 * tig;
        float2 bv0 = *reinterpret_cast<const float2*>(bias + o);
        float2 bv1 = *reinterpret_cast<const float2*>(bias + 768 + o);
        float2 bv2 = *reinterpret_cast<const float2*>(bias + 1536 + o);
        float2 bv3 = *reinterpret_cast<const float2*>(bias + 2304 + o);
#pragma unroll
        for (int mi = 0; mi < 2; mi++) {
#pragma unroll
            for (int h = 0; h < 2; h++) {
                int row = bm + wm + mi * 16 + g + 8 * h;
                float a0x = accA0[mi][ni][2*h], a0y = accA0[mi][ni][2*h+1];
                float a2x = accA1[mi][ni][2*h], a2y = accA1[mi][ni][2*h+1];
                float px  = accPQ[mi][ni][2*h],   py  = accPQ[mi][ni][2*h+1];
                float qx  = accPQ[mi][ni+2][2*h], qy  = accPQ[mi][ni+2][2*h+1];
                float sx = a0x + a2x, sy = a0y + a2y;
                float dx = a0x - a2x, dy = a0y - a2y;
                float* ob = out + (size_t)row * 3072;
                *reinterpret_cast<float2*>(ob + o)        = make_float2(sx + px + bv0.x, sy + py + bv0.y);
                *reinterpret_cast<float2*>(ob + 768 + o)  = make_float2(dx + qx + bv1.x, dy + qy + bv1.y);
                *reinterpret_cast<float2*>(ob + 1536 + o) = make_float2(sx - px + bv2.x, sy - py + bv2.y);
                *reinterpret_cast<float2*>(ob + 2304 + o) = make_float2(dx - qx + bv3.x, dy - qy + bv3.y);
            }
        }
    }
}

// ---------------------------------------------------------------------------
extern "C" void kernel_launch(void* const* d_in, const int* in_sizes, int n_in,
                              void* d_out, int out_size) {
    const float* x    = (const float*)d_in[0];
    const float* w    = (const float*)d_in[1];
    const float* bias = (const float*)d_in[2];
    float* out = (float*)d_out;

    cudaFuncSetAttribute(gemm_fused_kernel,
                         cudaFuncAttributeMaxDynamicSharedMemorySize, SMEM_BYTES);

    prep_xt_kernel<<<(M_DIM * 24) / 128, 128>>>(x);     // 1176 blocks
    prep_bp_kernel<<<(24 * 1152) / 256, 256>>>(w);      // 108 blocks

    dim3 grid(24, 49);
    gemm_fused_kernel<<<grid, 256, SMEM_BYTES>>>(bias, out);
}

// round 6
// speedup vs baseline: 1.1684x; 1.1150x over previous
#include <cuda_runtime.h>
#include <cuda_fp16.h>
#include <cstdint>

// HypercomplexLinear via DFT-4 diagonalization + fp16 mma.sync (m16n8k16) GEMM.
//   a0 = X0@W0'^T/4 (K=192), a2 = X2@W2'^T/4 (K=192),
//   P = (Xr@Wr^T - Xs@Ws^T)/2, Q = (Xr@Ws^T + Xs@Wr^T)/2   (K=384 each)
//   out_0=a0+a2+P, out_1=a0-a2+Q, out_2=a0+a2-P, out_3=a0-a2-Q  (+bias)
// G = [Out0 | Out2 | P | Q] fp32 intermediate, then combine pass.
// fp16 inputs (11-bit significand == tf32), fp32 accumulation.

#define M_DIM 6272
#define KX    768

// k within each 16-group permuted so fragment pairs (p, p+4) of half2 are
// adjacent words: stored half index = (2*(p&3)+(p>>2))*2 + h,  p=k>>1, h=k&1.
__device__ __half g_Xt[M_DIM * KX];        // [X0|X2|Xr|Xs]
// g_Bp: a0 tiles [0,147456): 6 x (3 chunks x 128n x 64k)
//       a2 tiles [147456, 294912)
//       PQ tiles [294912, ...): 12 x (6 chunks x 128n x 64k)  (0..5=P, 6..11=Q)
__device__ __half g_Bp[884736];
__device__ float  g_G[M_DIM * 3072];       // [Out0|Out2|P|Q]

__device__ __forceinline__ int kperm16(int kk) {   // kk in 0..15 -> stored idx
    int p = kk >> 1, h = kk & 1;
    return (2 * (p & 3) + (p >> 2)) * 2 + h;
}

// ---------------------------------------------------------------------------
// Prep 1: X DFT4 -> fp16, k-permuted. One thread per 16-k group per row.
// ---------------------------------------------------------------------------
__global__ void prep_xt_kernel(const float* __restrict__ x) {
    int idx = blockIdx.x * blockDim.x + threadIdx.x;   // 6272*12
    int b   = idx / 12;
    int g16 = (idx - b * 12) * 16;
    const float* xb = x + (size_t)b * KX;
    float v[4][16];
#pragma unroll
    for (int j = 0; j < 4; j++)
#pragma unroll
        for (int q = 0; q < 4; q++) {
            float4 u = *reinterpret_cast<const float4*>(xb + j * 192 + g16 + q * 4);
            v[j][q*4+0] = u.x; v[j][q*4+1] = u.y; v[j][q*4+2] = u.z; v[j][q*4+3] = u.w;
        }
    float comp[4][16];
#pragma unroll
    for (int k = 0; k < 16; k++) {
        float e = v[0][k] + v[2][k], o = v[1][k] + v[3][k];
        comp[0][k] = e + o;
        comp[1][k] = e - o;
        comp[2][k] = v[0][k] - v[2][k];
        comp[3][k] = v[1][k] - v[3][k];
    }
#pragma unroll
    for (int cmp = 0; cmp < 4; cmp++) {
        __half h[16];
#pragma unroll
        for (int k = 0; k < 16; k++) h[kperm16(k)] = __float2half_rn(comp[cmp][k]);
        uint4* dst = reinterpret_cast<uint4*>(g_Xt + (size_t)b * KX + cmp * 192 + g16);
        dst[0] = reinterpret_cast<const uint4*>(h)[0];
        dst[1] = reinterpret_cast<const uint4*>(h)[1];
    }
}

// ---------------------------------------------------------------------------
// Prep 2: pack weights -> fp16, k-permuted, [n][64k] rows per chunk.
// ---------------------------------------------------------------------------
__global__ void prep_bp_kernel(const float* __restrict__ w) {
    int idx = blockIdx.x * blockDim.x + threadIdx.x;   // 13824
    float val[64];
    __half* dst;
    if (idx < 4608) {                       // a0 / a2
        int cmp  = idx / 2304;              // 0: a0, 1: a2
        int rr   = idx - cmp * 2304;
        int tile = rr / 384;
        int rem  = rr - tile * 384;
        int cc   = rem >> 7;                // chunk 0..2
        int n    = rem & 127;
        int o    = tile * 128 + n;
        const float* b0 = w + o * 192 + cc * 64;
        float sg = cmp ? -1.0f : 1.0f;
#pragma unroll 8
        for (int kk = 0; kk < 64; kk++) {
            float w0 = b0[kk], w1 = b0[147456 + kk];
            float w2 = b0[294912 + kk], w3 = b0[442368 + kk];
            val[kk] = 0.25f * (w0 + sg * w1 + w2 + sg * w3);
        }
        dst = g_Bp + cmp * 147456 + tile * 24576 + cc * 8192 + n * 64;
    } else {                                // PQ
        int i2   = idx - 4608;              // 0..9215
        int t12  = i2 / 768;                // 0..11  (0..5 P, 6..11 Q)
        int rem  = i2 - t12 * 768;
        int cc   = rem >> 7;                // chunk 0..5
        int n    = rem & 127;
        int isQ  = t12 >= 6;
        int o    = (t12 % 6) * 128 + n;
        int ccx  = (cc < 3 ? cc : cc - 3) * 64;
        const float* b0 = w + o * 192 + ccx;
#pragma unroll 8
        for (int kk = 0; kk < 64; kk++) {
            float d02 = b0[kk] - b0[294912 + kk];           // Wr-ish
            float d13 = b0[147456 + kk] - b0[442368 + kk];  // Ws-ish
            float pv, qv;
            if (cc < 3) { pv = 0.5f * d02;  qv = 0.5f * d13; }   // Xr rows
            else        { pv = -0.5f * d13; qv = 0.5f * d02; }   // Xs rows
            val[kk] = isQ ? qv : pv;
        }
        dst = g_Bp + 294912 + t12 * 49152 + cc * 8192 + n * 64;
    }
    __half h[64];
#pragma unroll
    for (int kk = 0; kk < 64; kk++) {
        int kg = kk >> 4;
        h[kg * 16 + kperm16(kk & 15)] = __float2half_rn(val[kk]);
    }
#pragma unroll
    for (int q = 0; q < 8; q++)
        reinterpret_cast<uint4*>(dst)[q] = reinterpret_cast<const uint4*>(h)[q];
}

// ---------------------------------------------------------------------------
// fp16 GEMM: G = X @ B, 3-stage cp.async, CTA 128x128, K-chunk 64.
// Stage: A 128x64 fp16 (16KB) + B 128x64 fp16 (16KB), XOR-8 word swizzle.
// ---------------------------------------------------------------------------
#define STAGES 3
#define STG_B 32768
#define SMEM_BYTES (STAGES * STG_B)

__device__ __forceinline__ void mma_f16(float* c, uint32_t a0, uint32_t a1,
                                        uint32_t a2, uint32_t a3,
                                        uint32_t b0, uint32_t b1) {
    asm volatile(
        "mma.sync.aligned.m16n8k16.row.col.f32.f16.f16.f32 "
        "{%0,%1,%2,%3}, {%4,%5,%6,%7}, {%8,%9}, {%0,%1,%2,%3};"
        : "+f"(c[0]), "+f"(c[1]), "+f"(c[2]), "+f"(c[3])
        : "r"(a0), "r"(a1), "r"(a2), "r"(a3), "r"(b0), "r"(b1));
}

__global__ __launch_bounds__(256)
void gemm_f16_kernel() {
    extern __shared__ char smem[];
    const int nt  = blockIdx.x;          // 0..23
    const int bm  = blockIdx.y * 128;
    const int bn  = nt * 128;            // G column base

    int aoff, KT;
    const __half* Bg;
    if (nt < 6)       { aoff = 0;   KT = 3; Bg = g_Bp + nt * 24576; }
    else if (nt < 12) { aoff = 192; KT = 3; Bg = g_Bp + 147456 + (nt - 6) * 24576; }
    else              { aoff = 384; KT = 6; Bg = g_Bp + 294912 + (nt - 12) * 49152; }

    const int tid  = threadIdx.x;
    const int warp = tid >> 5;
    const int lane = tid & 31;
    const int g    = lane >> 2;
    const int tig  = lane & 3;
    const int wm   = (warp & 1) * 64;
    const int wn   = (warp >> 1) * 32;

    float acc[4][4][4];
#pragma unroll
    for (int mi = 0; mi < 4; mi++)
#pragma unroll
        for (int ni = 0; ni < 4; ni++)
#pragma unroll
            for (int r = 0; r < 4; r++) acc[mi][ni][r] = 0.0f;

    // loader: thread -> (row 0..127, 4 x 16B chunks)
    const int lrow = tid >> 1;
    const int cseg = (tid & 1) * 4;
    const char* gA = reinterpret_cast<const char*>(
        g_Xt + (size_t)(bm + lrow) * KX + aoff);
    const char* gB = reinterpret_cast<const char*>(Bg + lrow * 64);
    uint32_t sbase;
    asm("{ .reg .u64 t; cvta.to.shared.u64 t, %1; cvt.u32.u64 %0, t; }"
        : "=r"(sbase) : "l"(smem));
    const int wsw_store = (lrow & 3) << 3;

    auto load_stage = [&](int kt, int s) {
        uint32_t ab = sbase + (uint32_t)(s * STG_B);
        uint32_t bb = ab + 16384u;
#pragma unroll
        for (int f = 0; f < 4; f++) {
            int c = cseg + f;
            uint32_t wd = (uint32_t)(lrow * 32 + ((4 * c) ^ wsw_store)) * 4u;
            asm volatile("cp.async.cg.shared.global [%0], [%1], 16;"
                         :: "r"(ab + wd), "l"(gA + kt * 128 + c * 16));
            asm volatile("cp.async.cg.shared.global [%0], [%1], 16;"
                         :: "r"(bb + wd), "l"(gB + kt * 16384 + c * 16));
        }
    };

    const int fsw = (g & 3) << 3;

    auto compute = [&](int s) {
        const float* As = reinterpret_cast<const float*>(smem + s * STG_B);
        const float* Bs = As + 4096;
#pragma unroll
        for (int kg = 0; kg < 4; kg++) {
            int wo = ((kg << 3) + 2 * tig) ^ fsw;
            float2 a[4][2];
#pragma unroll
            for (int mi = 0; mi < 4; mi++) {
                int row = wm + mi * 16 + g;
                a[mi][0] = *reinterpret_cast<const float2*>(As + row * 32 + wo);
                a[mi][1] = *reinterpret_cast<const float2*>(As + (row + 8) * 32 + wo);
            }
#pragma unroll
            for (int ni = 0; ni < 4; ni++) {
                int col = wn + ni * 8 + g;
                float2 b = *reinterpret_cast<const float2*>(Bs + col * 32 + wo);
#pragma unroll
                for (int mi = 0; mi < 4; mi++)
                    mma_f16(acc[mi][ni],
                            __float_as_uint(a[mi][0].x), __float_as_uint(a[mi][1].x),
                            __float_as_uint(a[mi][0].y), __float_as_uint(a[mi][1].y),
                            __float_as_uint(b.x), __float_as_uint(b.y));
            }
        }
    };

    int fetch = 0;
#pragma unroll
    for (int s = 0; s < STAGES - 1; s++) {
        if (fetch < KT) load_stage(fetch, s);
        asm volatile("cp.async.commit_group;");
        fetch++;
    }
    asm volatile("cp.async.wait_group %0;" :: "n"(STAGES - 2));
    __syncthreads();

    for (int kt = 0; kt < KT; kt++) {
        if (fetch < KT) load_stage(fetch, fetch % STAGES);
        asm volatile("cp.async.commit_group;");
        fetch++;
        compute(kt % STAGES);
        asm volatile("cp.async.wait_group %0;" :: "n"(STAGES - 2));
        __syncthreads();
    }

    // Epilogue: store raw G
#pragma unroll
    for (int mi = 0; mi < 4; mi++) {
        int row0 = bm + wm + mi * 16 + g;
#pragma unroll
        for (int ni = 0; ni < 4; ni++) {
            int col = bn + wn + ni * 8 + 2 * tig;
            *reinterpret_cast<float2*>(&g_G[(size_t)row0 * 3072 + col]) =
                make_float2(acc[mi][ni][0], acc[mi][ni][1]);
            *reinterpret_cast<float2*>(&g_G[(size_t)(row0 + 8) * 3072 + col]) =
                make_float2(acc[mi][ni][2], acc[mi][ni][3]);
        }
    }
}

// ---------------------------------------------------------------------------
// Combine: out_k from Out0/Out2/P/Q + bias.
// ---------------------------------------------------------------------------
__global__ void combine_kernel(const float* __restrict__ bias,
                               float* __restrict__ out) {
    int idx = blockIdx.x * blockDim.x + threadIdx.x;   // 6272*192
    int b  = idx / 192;
    int o4 = idx - b * 192;
    const float4* Gr = reinterpret_cast<const float4*>(g_G + (size_t)b * 3072);
    float4 a0 = Gr[o4];
    float4 a2 = Gr[192 + o4];
    float4 p  = Gr[384 + o4];
    float4 q  = Gr[576 + o4];
    const float4* bs = reinterpret_cast<const float4*>(bias);
    float4 b0 = bs[o4], b1 = bs[192 + o4], b2 = bs[384 + o4], b3 = bs[576 + o4];

    float4 s = make_float4(a0.x+a2.x, a0.y+a2.y, a0.z+a2.z, a0.w+a2.w);
    float4 d = make_float4(a0.x-a2.x, a0.y-a2.y, a0.z-a2.z, a0.w-a2.w);

    float4* ob = reinterpret_cast<float4*>(out + (size_t)b * 3072);
    ob[o4]       = make_float4(s.x+p.x+b0.x, s.y+p.y+b0.y, s.z+p.z+b0.z, s.w+p.w+b0.w);
    ob[192 + o4] = make_float4(d.x+q.x+b1.x, d.y+q.y+b1.y, d.z+q.z+b1.z, d.w+q.w+b1.w);
    ob[384 + o4] = make_float4(s.x-p.x+b2.x, s.y-p.y+b2.y, s.z-p.z+b2.z, s.w-p.w+b2.w);
    ob[576 + o4] = make_float4(d.x-q.x+b3.x, d.y-q.y+b3.y, d.z-q.z+b3.z, d.w-q.w+b3.w);
}

// ---------------------------------------------------------------------------
extern "C" void kernel_launch(void* const* d_in, const int* in_sizes, int n_in,
                              void* d_out, int out_size) {
    const float* x    = (const float*)d_in[0];
    const float* w    = (const float*)d_in[1];
    const float* bias = (const float*)d_in[2];
    float* out = (float*)d_out;

    cudaFuncSetAttribute(gemm_f16_kernel,
                         cudaFuncAttributeMaxDynamicSharedMemorySize, SMEM_BYTES);

    prep_xt_kernel<<<(M_DIM * 12) / 128, 128>>>(x);     // 588 blocks
    prep_bp_kernel<<<13824 / 128, 128>>>(w);            // 108 blocks

    dim3 grid(24, 49);
    gemm_f16_kernel<<<grid, 256, SMEM_BYTES>>>();

    combine_kernel<<<(M_DIM * 192) / 256, 256>>>(bias, out);
}

// round 7
// speedup vs baseline: 1.1947x; 1.0225x over previous
#include <cuda_runtime.h>
#include <cuda_fp16.h>
#include <cstdint>

// HypercomplexLinear via DFT-4 diagonalization + fp16 mma.sync m16n8k16.
//   a0 = X0@W0'^T/4 (K=192), a2 = X2@W2'^T/4 (K=192),
//   P = (Xr@Wr^T - Xs@Ws^T)/2, Q = (Xr@Ws^T + Xs@Wr^T)/2   (K=384)
//   out_0=a0+a2+P, out_1=a0-a2+Q, out_2=a0+a2-P, out_3=a0-a2-Q  (+bias)
// G = [Out0|Out2|P|Q] fp16 intermediate, combine pass to fp32 out.

#define M_DIM 6272
#define KX    768

__device__ __half g_Xt[M_DIM * KX];   // [X0|X2|Xr|Xs], canonical k order
// a0 tiles [0,147456): 6 x (3 chunks x 128n x 64k); a2 [147456,294912);
// PQ [294912,...): 12 x (6 chunks x 128n x 64k)  (0..5=P, 6..11=Q)
__device__ __half g_Bp[884736];
__device__ __half g_G[M_DIM * 3072];  // fp16 intermediate

// ---------------------------------------------------------------------------
// Prep 1: X DFT4 -> fp16. One thread per 16-k group per row.
// ---------------------------------------------------------------------------
__global__ void prep_xt_kernel(const float* __restrict__ x) {
    int idx = blockIdx.x * blockDim.x + threadIdx.x;   // 6272*12
    int b   = idx / 12;
    int g16 = (idx - b * 12) * 16;
    const float* xb = x + (size_t)b * KX;
    float v[4][16];
#pragma unroll
    for (int j = 0; j < 4; j++)
#pragma unroll
        for (int q = 0; q < 4; q++) {
            float4 u = *reinterpret_cast<const float4*>(xb + j * 192 + g16 + q * 4);
            v[j][q*4+0] = u.x; v[j][q*4+1] = u.y; v[j][q*4+2] = u.z; v[j][q*4+3] = u.w;
        }
#pragma unroll
    for (int cmp = 0; cmp < 4; cmp++) {
        __half h[16];
#pragma unroll
        for (int k = 0; k < 16; k++) {
            float e = v[0][k] + v[2][k], o = v[1][k] + v[3][k];
            float c = (cmp == 0) ? e + o : (cmp == 1) ? e - o
                    : (cmp == 2) ? v[0][k] - v[2][k] : v[1][k] - v[3][k];
            h[k] = __float2half_rn(c);
        }
        uint4* dst = reinterpret_cast<uint4*>(g_Xt + (size_t)b * KX + cmp * 192 + g16);
        dst[0] = reinterpret_cast<const uint4*>(h)[0];
        dst[1] = reinterpret_cast<const uint4*>(h)[1];
    }
}

// ---------------------------------------------------------------------------
// Prep 2: pack weights -> fp16, [n][64k] rows per chunk, canonical k order.
// ---------------------------------------------------------------------------
__global__ void prep_bp_kernel(const float* __restrict__ w) {
    int idx = blockIdx.x * blockDim.x + threadIdx.x;   // 13824
    float val[64];
    __half* dst;
    if (idx < 4608) {                       // a0 / a2
        int cmp  = idx / 2304;
        int rr   = idx - cmp * 2304;
        int tile = rr / 384;
        int rem  = rr - tile * 384;
        int cc   = rem >> 7;                // chunk 0..2
        int n    = rem & 127;
        int o    = tile * 128 + n;
        const float* b0 = w + o * 192 + cc * 64;
        float sg = cmp ? -1.0f : 1.0f;
#pragma unroll 8
        for (int kk = 0; kk < 64; kk++) {
            float w0 = b0[kk], w1 = b0[147456 + kk];
            float w2 = b0[294912 + kk], w3 = b0[442368 + kk];
            val[kk] = 0.25f * (w0 + sg * w1 + w2 + sg * w3);
        }
        dst = g_Bp + cmp * 147456 + tile * 24576 + cc * 8192 + n * 64;
    } else {                                // PQ
        int i2   = idx - 4608;
        int t12  = i2 / 768;                // 0..11
        int rem  = i2 - t12 * 768;
        int cc   = rem >> 7;                // chunk 0..5
        int n    = rem & 127;
        int isQ  = t12 >= 6;
        int o    = (t12 % 6) * 128 + n;
        int ccx  = (cc < 3 ? cc : cc - 3) * 64;
        const float* b0 = w + o * 192 + ccx;
#pragma unroll 8
        for (int kk = 0; kk < 64; kk++) {
            float d02 = b0[kk] - b0[294912 + kk];
            float d13 = b0[147456 + kk] - b0[442368 + kk];
            float pv, qv;
            if (cc < 3) { pv = 0.5f * d02;  qv = 0.5f * d13; }
            else        { pv = -0.5f * d13; qv = 0.5f * d02; }
            val[kk] = isQ ? qv : pv;
        }
        dst = g_Bp + 294912 + t12 * 49152 + cc * 8192 + n * 64;
    }
    __half h[64];
#pragma unroll
    for (int kk = 0; kk < 64; kk++) h[kk] = __float2half_rn(val[kk]);
#pragma unroll
    for (int q = 0; q < 8; q++)
        reinterpret_cast<uint4*>(dst)[q] = reinterpret_cast<const uint4*>(h)[q];
}

// ---------------------------------------------------------------------------
// fp16 GEMM with ldmatrix. CTA 128x128, K-chunk 64, 3-stage cp.async.
// Smem row = 64 fp16 = 128B = 8 chunks of 16B; chunk stored at (c ^ (row&7)).
// ---------------------------------------------------------------------------
#define STAGES 3
#define STG_B 32768
#define SMEM_BYTES (STAGES * STG_B)

__device__ __forceinline__ void mma_f16(float* c, uint32_t a0, uint32_t a1,
                                        uint32_t a2, uint32_t a3,
                                        uint32_t b0, uint32_t b1) {
    asm volatile(
        "mma.sync.aligned.m16n8k16.row.col.f32.f16.f16.f32 "
        "{%0,%1,%2,%3}, {%4,%5,%6,%7}, {%8,%9}, {%0,%1,%2,%3};"
        : "+f"(c[0]), "+f"(c[1]), "+f"(c[2]), "+f"(c[3])
        : "r"(a0), "r"(a1), "r"(a2), "r"(a3), "r"(b0), "r"(b1));
}
#define LDSM_X4(r0, r1, r2, r3, a) \
    asm volatile("ldmatrix.sync.aligned.m8n8.x4.shared.b16 {%0,%1,%2,%3}, [%4];" \
                 : "=r"(r0), "=r"(r1), "=r"(r2), "=r"(r3) : "r"(a))

__global__ __launch_bounds__(256)
void gemm_f16_kernel() {
    extern __shared__ char smem[];
    const int nt  = blockIdx.x;          // 0..23
    const int bm  = blockIdx.y * 128;
    const int bn  = nt * 128;

    int aoff, KT;
    const __half* Bg;
    if (nt < 6)       { aoff = 0;   KT = 3; Bg = g_Bp + nt * 24576; }
    else if (nt < 12) { aoff = 192; KT = 3; Bg = g_Bp + 147456 + (nt - 6) * 24576; }
    else              { aoff = 384; KT = 6; Bg = g_Bp + 294912 + (nt - 12) * 49152; }

    const int tid  = threadIdx.x;
    const int warp = tid >> 5;
    const int lane = tid & 31;
    const int g    = lane >> 2;
    const int tig  = lane & 3;
    const int wm   = (warp & 1) * 64;
    const int wn   = (warp >> 1) * 32;

    float acc[4][4][4];
#pragma unroll
    for (int mi = 0; mi < 4; mi++)
#pragma unroll
        for (int ni = 0; ni < 4; ni++)
#pragma unroll
            for (int r = 0; r < 4; r++) acc[mi][ni][r] = 0.0f;

    // cp.async loader: 2 threads per row, 4 x 16B chunks each
    const int lrow = tid >> 1;
    const int cseg = (tid & 1) * 4;
    const int ssw  = lrow & 7;
    const char* gA = reinterpret_cast<const char*>(
        g_Xt + (size_t)(bm + lrow) * KX + aoff);
    const char* gB = reinterpret_cast<const char*>(Bg + lrow * 64);
    uint32_t sbase;
    asm("{ .reg .u64 t; cvta.to.shared.u64 t, %1; cvt.u32.u64 %0, t; }"
        : "=r"(sbase) : "l"(smem));

    auto load_stage = [&](int kt, int s) {
        uint32_t ab = sbase + (uint32_t)(s * STG_B);
        uint32_t bb = ab + 16384u;
#pragma unroll
        for (int f = 0; f < 4; f++) {
            int c = cseg + f;
            uint32_t wd = (uint32_t)(lrow * 128 + ((c ^ ssw) << 4));
            asm volatile("cp.async.cg.shared.global [%0], [%1], 16;"
                         :: "r"(ab + wd), "l"(gA + kt * 128 + c * 16));
            asm volatile("cp.async.cg.shared.global [%0], [%1], 16;"
                         :: "r"(bb + wd), "l"(gB + kt * 16384 + c * 16));
        }
    };

    // ldmatrix per-lane row mapping
    const int rowA = (lane & 7) + ((lane >> 3) & 1) * 8;
    const int chA  = lane >> 4;              // k-chunk half select
    const int rowB = (lane & 7) + ((lane >> 4) & 1) * 8;
    const int chB  = (lane >> 3) & 1;
    int rA[4], rB[2];
#pragma unroll
    for (int mi = 0; mi < 4; mi++) rA[mi] = wm + mi * 16 + rowA;
#pragma unroll
    for (int n2 = 0; n2 < 2; n2++) rB[n2] = wn + n2 * 16 + rowB;

    auto compute = [&](int s) {
        uint32_t As = sbase + (uint32_t)(s * STG_B);
        uint32_t Bs = As + 16384u;
#pragma unroll
        for (int kg = 0; kg < 4; kg++) {
            uint32_t af[4][4], bf[2][4];
#pragma unroll
            for (int mi = 0; mi < 4; mi++) {
                uint32_t ad = As + (uint32_t)(rA[mi] * 128
                            + (((2 * kg + chA) ^ (rA[mi] & 7)) << 4));
                LDSM_X4(af[mi][0], af[mi][1], af[mi][2], af[mi][3], ad);
            }
#pragma unroll
            for (int n2 = 0; n2 < 2; n2++) {
                uint32_t bd = Bs + (uint32_t)(rB[n2] * 128
                            + (((2 * kg + chB) ^ (rB[n2] & 7)) << 4));
                LDSM_X4(bf[n2][0], bf[n2][1], bf[n2][2], bf[n2][3], bd);
            }
#pragma unroll
            for (int ni = 0; ni < 4; ni++) {
                uint32_t b0 = bf[ni >> 1][(ni & 1) * 2];
                uint32_t b1 = bf[ni >> 1][(ni & 1) * 2 + 1];
#pragma unroll
                for (int mi = 0; mi < 4; mi++)
                    mma_f16(acc[mi][ni], af[mi][0], af[mi][1], af[mi][2], af[mi][3],
                            b0, b1);
            }
        }
    };

    int fetch = 0;
#pragma unroll
    for (int s = 0; s < STAGES - 1; s++) {
        if (fetch < KT) load_stage(fetch, s);
        asm volatile("cp.async.commit_group;");
        fetch++;
    }
    asm volatile("cp.async.wait_group %0;" :: "n"(STAGES - 2));
    __syncthreads();

    for (int kt = 0; kt < KT; kt++) {
        if (fetch < KT) load_stage(fetch, fetch % STAGES);
        asm volatile("cp.async.commit_group;");
        fetch++;
        compute(kt % STAGES);
        asm volatile("cp.async.wait_group %0;" :: "n"(STAGES - 2));
        __syncthreads();
    }

    // Epilogue: acc -> fp16 smem tile (row stride 136) -> coalesced stores
    __half* sg = reinterpret_cast<__half*>(smem);
#pragma unroll
    for (int mi = 0; mi < 4; mi++) {
        int row0 = wm + mi * 16 + g;
#pragma unroll
        for (int ni = 0; ni < 4; ni++) {
            int col = wn + ni * 8 + 2 * tig;
            *reinterpret_cast<__half2*>(sg + row0 * 136 + col) =
                __floats2half2_rn(acc[mi][ni][0], acc[mi][ni][1]);
            *reinterpret_cast<__half2*>(sg + (row0 + 8) * 136 + col) =
                __floats2half2_rn(acc[mi][ni][2], acc[mi][ni][3]);
        }
    }
    __syncthreads();
#pragma unroll
    for (int i = 0; i < 8; i++) {
        int linear = tid + 256 * i;
        int row = linear >> 4;
        int q   = linear & 15;
        uint4 v = *reinterpret_cast<const uint4*>(sg + row * 136 + q * 8);
        *reinterpret_cast<uint4*>(g_G + (size_t)(bm + row) * 3072 + bn + q * 8) = v;
    }
}

// ---------------------------------------------------------------------------
// Combine: fp16 G -> fp32 out with bias. One thread per (b, 8 o).
// ---------------------------------------------------------------------------
__global__ void combine_kernel(const float* __restrict__ bias,
                               float* __restrict__ out) {
    int idx = blockIdx.x * blockDim.x + threadIdx.x;   // 6272*96
    int b  = idx / 96;
    int o8 = (idx - b * 96) * 8;
    const __half* Gb = g_G + (size_t)b * 3072;
    __half2 a0[4], a2[4], p[4], q[4];
    *reinterpret_cast<uint4*>(a0) = *reinterpret_cast<const uint4*>(Gb + o8);
    *reinterpret_cast<uint4*>(a2) = *reinterpret_cast<const uint4*>(Gb + 768 + o8);
    *reinterpret_cast<uint4*>(p)  = *reinterpret_cast<const uint4*>(Gb + 1536 + o8);
    *reinterpret_cast<uint4*>(q)  = *reinterpret_cast<const uint4*>(Gb + 2304 + o8);

    float r0[8], r1[8], r2[8], r3[8];
#pragma unroll
    for (int i = 0; i < 4; i++) {
        float2 fa0 = __half22float2(a0[i]);
        float2 fa2 = __half22float2(a2[i]);
        float2 fp  = __half22float2(p[i]);
        float2 fq  = __half22float2(q[i]);
        float sx = fa0.x + fa2.x, sy = fa0.y + fa2.y;
        float dx = fa0.x - fa2.x, dy = fa0.y - fa2.y;
        r0[2*i] = sx + fp.x; r0[2*i+1] = sy + fp.y;
        r1[2*i] = dx + fq.x; r1[2*i+1] = dy + fq.y;
        r2[2*i] = sx - fp.x; r2[2*i+1] = sy - fp.y;
        r3[2*i] = dx - fq.x; r3[2*i+1] = dy - fq.y;
    }
    float* ob = out + (size_t)b * 3072;
#pragma unroll
    for (int c = 0; c < 4; c++) {
        const float* rr = (c == 0) ? r0 : (c == 1) ? r1 : (c == 2) ? r2 : r3;
        const float* bv = bias + c * 768 + o8;
        float4 v0 = make_float4(rr[0]+bv[0], rr[1]+bv[1], rr[2]+bv[2], rr[3]+bv[3]);
        float4 v1 = make_float4(rr[4]+bv[4], rr[5]+bv[5], rr[6]+bv[6], rr[7]+bv[7]);
        *reinterpret_cast<float4*>(ob + c * 768 + o8)     = v0;
        *reinterpret_cast<float4*>(ob + c * 768 + o8 + 4) = v1;
    }
}

// ---------------------------------------------------------------------------
extern "C" void kernel_launch(void* const* d_in, const int* in_sizes, int n_in,
                              void* d_out, int out_size) {
    const float* x    = (const float*)d_in[0];
    const float* w    = (const float*)d_in[1];
    const float* bias = (const float*)d_in[2];
    float* out = (float*)d_out;

    cudaFuncSetAttribute(gemm_f16_kernel,
                         cudaFuncAttributeMaxDynamicSharedMemorySize, SMEM_BYTES);

    prep_xt_kernel<<<(M_DIM * 12) / 128, 128>>>(x);     // 588 blocks
    prep_bp_kernel<<<13824 / 128, 128>>>(w);            // 108 blocks

    dim3 grid(24, 49);
    gemm_f16_kernel<<<grid, 256, SMEM_BYTES>>>();

    combine_kernel<<<(M_DIM * 96) / 256, 256>>>(bias, out);  // 2352 blocks
}

// round 8
// speedup vs baseline: 1.3783x; 1.1537x over previous
#include <cuda_runtime.h>
#include <cuda_fp16.h>
#include <cstdint>

// HypercomplexLinear via DFT-4 diagonalization + fp16 mma.sync m16n8k16.
//   a0 = X0@W0'^T/4 (K=192), a2 = X2@W2'^T/4 (K=192),
//   P = (Xr@Wr^T - Xs@Ws^T)/2, Q = (Xr@Ws^T + Xs@Wr^T)/2   (K=384)
//   out_0=a0+a2+P, out_1=a0-a2+Q, out_2=a0+a2-P, out_3=a0-a2-Q  (+bias)
// G = [Out0|Out2|P|Q] fp16 intermediate, combine pass to fp32 out.

#define M_DIM 6272
#define KX    768

__device__ __half g_Xt[M_DIM * KX];   // [X0|X2|Xr|Xs], canonical k order
// a0 tiles [0,147456): 6 x (3 chunks x 128n x 64k); a2 [147456,294912);
// PQ [294912,...): 12 x (6 chunks x 128n x 64k)  (0..5=P, 6..11=Q)
__device__ __half g_Bp[884736];
__device__ __half g_G[M_DIM * 3072];  // fp16 intermediate

// ---------------------------------------------------------------------------
// Prep 1: X DFT4 -> fp16. One thread per 8 c per row (150k threads).
// ---------------------------------------------------------------------------
__global__ void prep_xt_kernel(const float* __restrict__ x) {
    int idx = blockIdx.x * blockDim.x + threadIdx.x;   // 6272*24
    int b   = idx / 24;
    int c8  = (idx - b * 24) * 8;
    const float* xb = x + (size_t)b * KX;
    float v[4][8];
#pragma unroll
    for (int j = 0; j < 4; j++) {
        float4 u0 = *reinterpret_cast<const float4*>(xb + j * 192 + c8);
        float4 u1 = *reinterpret_cast<const float4*>(xb + j * 192 + c8 + 4);
        v[j][0]=u0.x; v[j][1]=u0.y; v[j][2]=u0.z; v[j][3]=u0.w;
        v[j][4]=u1.x; v[j][5]=u1.y; v[j][6]=u1.z; v[j][7]=u1.w;
    }
#pragma unroll
    for (int cmp = 0; cmp < 4; cmp++) {
        __half h[8];
#pragma unroll
        for (int k = 0; k < 8; k++) {
            float e = v[0][k] + v[2][k], o = v[1][k] + v[3][k];
            float c = (cmp == 0) ? e + o : (cmp == 1) ? e - o
                    : (cmp == 2) ? v[0][k] - v[2][k] : v[1][k] - v[3][k];
            h[k] = __float2half_rn(c);
        }
        *reinterpret_cast<uint4*>(g_Xt + (size_t)b * KX + cmp * 192 + c8) =
            *reinterpret_cast<const uint4*>(h);
    }
}

// ---------------------------------------------------------------------------
// Prep 2: pack weights -> fp16, [n][64k] rows per chunk, canonical k order.
// ---------------------------------------------------------------------------
__global__ void prep_bp_kernel(const float* __restrict__ w) {
    int idx = blockIdx.x * blockDim.x + threadIdx.x;   // 13824
    float val[64];
    __half* dst;
    if (idx < 4608) {                       // a0 / a2
        int cmp  = idx / 2304;
        int rr   = idx - cmp * 2304;
        int tile = rr / 384;
        int rem  = rr - tile * 384;
        int cc   = rem >> 7;                // chunk 0..2
        int n    = rem & 127;
        int o    = tile * 128 + n;
        const float* b0 = w + o * 192 + cc * 64;
        float sg = cmp ? -1.0f : 1.0f;
#pragma unroll 8
        for (int kk = 0; kk < 64; kk++) {
            float w0 = b0[kk], w1 = b0[147456 + kk];
            float w2 = b0[294912 + kk], w3 = b0[442368 + kk];
            val[kk] = 0.25f * (w0 + sg * w1 + w2 + sg * w3);
        }
        dst = g_Bp + cmp * 147456 + tile * 24576 + cc * 8192 + n * 64;
    } else {                                // PQ
        int i2   = idx - 4608;
        int t12  = i2 / 768;                // 0..11
        int rem  = i2 - t12 * 768;
        int cc   = rem >> 7;                // chunk 0..5
        int n    = rem & 127;
        int isQ  = t12 >= 6;
        int o    = (t12 % 6) * 128 + n;
        int ccx  = (cc < 3 ? cc : cc - 3) * 64;
        const float* b0 = w + o * 192 + ccx;
#pragma unroll 8
        for (int kk = 0; kk < 64; kk++) {
            float d02 = b0[kk] - b0[294912 + kk];
            float d13 = b0[147456 + kk] - b0[442368 + kk];
            float pv, qv;
            if (cc < 3) { pv = 0.5f * d02;  qv = 0.5f * d13; }
            else        { pv = -0.5f * d13; qv = 0.5f * d02; }
            val[kk] = isQ ? qv : pv;
        }
        dst = g_Bp + 294912 + t12 * 49152 + cc * 8192 + n * 64;
    }
    __half h[64];
#pragma unroll
    for (int kk = 0; kk < 64; kk++) h[kk] = __float2half_rn(val[kk]);
#pragma unroll
    for (int q = 0; q < 8; q++)
        reinterpret_cast<uint4*>(dst)[q] = reinterpret_cast<const uint4*>(h)[q];
}

// ---------------------------------------------------------------------------
// fp16 GEMM with ldmatrix. CTA 128x128, K-chunk 64, 3-stage cp.async.
// 2 CTAs/SM (96KB smem each). Heavy (K=384) tiles scheduled first.
// ---------------------------------------------------------------------------
#define STAGES 3
#define STG_B 32768
#define SMEM_BYTES (STAGES * STG_B)

__device__ __forceinline__ void mma_f16(float* c, uint32_t a0, uint32_t a1,
                                        uint32_t a2, uint32_t a3,
                                        uint32_t b0, uint32_t b1) {
    asm volatile(
        "mma.sync.aligned.m16n8k16.row.col.f32.f16.f16.f32 "
        "{%0,%1,%2,%3}, {%4,%5,%6,%7}, {%8,%9}, {%0,%1,%2,%3};"
        : "+f"(c[0]), "+f"(c[1]), "+f"(c[2]), "+f"(c[3])
        : "r"(a0), "r"(a1), "r"(a2), "r"(a3), "r"(b0), "r"(b1));
}
#define LDSM_X4(r0, r1, r2, r3, a) \
    asm volatile("ldmatrix.sync.aligned.m8n8.x4.shared.b16 {%0,%1,%2,%3}, [%4];" \
                 : "=r"(r0), "=r"(r1), "=r"(r2), "=r"(r3) : "r"(a))

__global__ __launch_bounds__(256, 2)
void gemm_f16_kernel() {
    extern __shared__ char smem[];
    const int nt  = (blockIdx.x + 12) % 24;   // heavy PQ tiles (12..23) first
    const int bm  = blockIdx.y * 128;
    const int bn  = nt * 128;

    int aoff, KT;
    const __half* Bg;
    if (nt < 6)       { aoff = 0;   KT = 3; Bg = g_Bp + nt * 24576; }
    else if (nt < 12) { aoff = 192; KT = 3; Bg = g_Bp + 147456 + (nt - 6) * 24576; }
    else              { aoff = 384; KT = 6; Bg = g_Bp + 294912 + (nt - 12) * 49152; }

    const int tid  = threadIdx.x;
    const int warp = tid >> 5;
    const int lane = tid & 31;
    const int g    = lane >> 2;
    const int tig  = lane & 3;
    const int wm   = (warp & 1) * 64;
    const int wn   = (warp >> 1) * 32;

    float acc[4][4][4];
#pragma unroll
    for (int mi = 0; mi < 4; mi++)
#pragma unroll
        for (int ni = 0; ni < 4; ni++)
#pragma unroll
            for (int r = 0; r < 4; r++) acc[mi][ni][r] = 0.0f;

    // cp.async loader: 2 threads per row, 4 x 16B chunks each
    const int lrow = tid >> 1;
    const int cseg = (tid & 1) * 4;
    const int ssw  = lrow & 7;
    const char* gA = reinterpret_cast<const char*>(
        g_Xt + (size_t)(bm + lrow) * KX + aoff);
    const char* gB = reinterpret_cast<const char*>(Bg + lrow * 64);
    uint32_t sbase;
    asm("{ .reg .u64 t; cvta.to.shared.u64 t, %1; cvt.u32.u64 %0, t; }"
        : "=r"(sbase) : "l"(smem));

    auto load_stage = [&](int kt, int s) {
        uint32_t ab = sbase + (uint32_t)(s * STG_B);
        uint32_t bb = ab + 16384u;
#pragma unroll
        for (int f = 0; f < 4; f++) {
            int c = cseg + f;
            uint32_t wd = (uint32_t)(lrow * 128 + ((c ^ ssw) << 4));
            asm volatile("cp.async.cg.shared.global [%0], [%1], 16;"
                         :: "r"(ab + wd), "l"(gA + kt * 128 + c * 16));
            asm volatile("cp.async.cg.shared.global [%0], [%1], 16;"
                         :: "r"(bb + wd), "l"(gB + kt * 16384 + c * 16));
        }
    };

    // ldmatrix per-lane row mapping
    const int rowA = (lane & 7) + ((lane >> 3) & 1) * 8;
    const int chA  = lane >> 4;
    const int rowB = (lane & 7) + ((lane >> 4) & 1) * 8;
    const int chB  = (lane >> 3) & 1;
    int rA[4], rB[2];
#pragma unroll
    for (int mi = 0; mi < 4; mi++) rA[mi] = wm + mi * 16 + rowA;
#pragma unroll
    for (int n2 = 0; n2 < 2; n2++) rB[n2] = wn + n2 * 16 + rowB;

    auto compute = [&](int s) {
        uint32_t As = sbase + (uint32_t)(s * STG_B);
        uint32_t Bs = As + 16384u;
#pragma unroll
        for (int kg = 0; kg < 4; kg++) {
            uint32_t af[4][4], bf[2][4];
#pragma unroll
            for (int mi = 0; mi < 4; mi++) {
                uint32_t ad = As + (uint32_t)(rA[mi] * 128
                            + (((2 * kg + chA) ^ (rA[mi] & 7)) << 4));
                LDSM_X4(af[mi][0], af[mi][1], af[mi][2], af[mi][3], ad);
            }
#pragma unroll
            for (int n2 = 0; n2 < 2; n2++) {
                uint32_t bd = Bs + (uint32_t)(rB[n2] * 128
                            + (((2 * kg + chB) ^ (rB[n2] & 7)) << 4));
                LDSM_X4(bf[n2][0], bf[n2][1], bf[n2][2], bf[n2][3], bd);
            }
#pragma unroll
            for (int ni = 0; ni < 4; ni++) {
                uint32_t b0 = bf[ni >> 1][(ni & 1) * 2];
                uint32_t b1 = bf[ni >> 1][(ni & 1) * 2 + 1];
#pragma unroll
                for (int mi = 0; mi < 4; mi++)
                    mma_f16(acc[mi][ni], af[mi][0], af[mi][1], af[mi][2], af[mi][3],
                            b0, b1);
            }
        }
    };

    int fetch = 0;
#pragma unroll
    for (int s = 0; s < STAGES - 1; s++) {
        if (fetch < KT) load_stage(fetch, s);
        asm volatile("cp.async.commit_group;");
        fetch++;
    }
    asm volatile("cp.async.wait_group %0;" :: "n"(STAGES - 2));
    __syncthreads();

    for (int kt = 0; kt < KT; kt++) {
        if (fetch < KT) load_stage(fetch, fetch % STAGES);
        asm volatile("cp.async.commit_group;");
        fetch++;
        compute(kt % STAGES);
        asm volatile("cp.async.wait_group %0;" :: "n"(STAGES - 2));
        __syncthreads();
    }

    // Epilogue: acc -> fp16 smem tile (row stride 136) -> coalesced stores
    __half* sg = reinterpret_cast<__half*>(smem);
#pragma unroll
    for (int mi = 0; mi < 4; mi++) {
        int row0 = wm + mi * 16 + g;
#pragma unroll
        for (int ni = 0; ni < 4; ni++) {
            int col = wn + ni * 8 + 2 * tig;
            *reinterpret_cast<__half2*>(sg + row0 * 136 + col) =
                __floats2half2_rn(acc[mi][ni][0], acc[mi][ni][1]);
            *reinterpret_cast<__half2*>(sg + (row0 + 8) * 136 + col) =
                __floats2half2_rn(acc[mi][ni][2], acc[mi][ni][3]);
        }
    }
    __syncthreads();
#pragma unroll
    for (int i = 0; i < 8; i++) {
        int linear = tid + 256 * i;
        int row = linear >> 4;
        int q   = linear & 15;
        uint4 v = *reinterpret_cast<const uint4*>(sg + row * 136 + q * 8);
        *reinterpret_cast<uint4*>(g_G + (size_t)(bm + row) * 3072 + bn + q * 8) = v;
    }
}

// ---------------------------------------------------------------------------
// Combine: fp16 G -> fp32 out with bias. One thread per (b, 4 o) — 1.2M thr.
// ---------------------------------------------------------------------------
__global__ void combine_kernel(const float* __restrict__ bias,
                               float* __restrict__ out) {
    int idx = blockIdx.x * blockDim.x + threadIdx.x;   // 6272*192
    int b  = idx / 192;
    int o4 = (idx - b * 192) * 4;
    const __half* Gb = g_G + (size_t)b * 3072;
    __half2 a0[2], a2[2], p[2], q[2];
    *reinterpret_cast<uint2*>(a0) = *reinterpret_cast<const uint2*>(Gb + o4);
    *reinterpret_cast<uint2*>(a2) = *reinterpret_cast<const uint2*>(Gb + 768 + o4);
    *reinterpret_cast<uint2*>(p)  = *reinterpret_cast<const uint2*>(Gb + 1536 + o4);
    *reinterpret_cast<uint2*>(q)  = *reinterpret_cast<const uint2*>(Gb + 2304 + o4);

    float r0[4], r1[4], r2[4], r3[4];
#pragma unroll
    for (int i = 0; i < 2; i++) {
        float2 fa0 = __half22float2(a0[i]);
        float2 fa2 = __half22float2(a2[i]);
        float2 fp  = __half22float2(p[i]);
        float2 fq  = __half22float2(q[i]);
        float sx = fa0.x + fa2.x, sy = fa0.y + fa2.y;
        float dx = fa0.x - fa2.x, dy = fa0.y - fa2.y;
        r0[2*i] = sx + fp.x; r0[2*i+1] = sy + fp.y;
        r1[2*i] = dx + fq.x; r1[2*i+1] = dy + fq.y;
        r2[2*i] = sx - fp.x; r2[2*i+1] = sy - fp.y;
        r3[2*i] = dx - fq.x; r3[2*i+1] = dy - fq.y;
    }
    float* ob = out + (size_t)b * 3072 + o4;
    const float4 bv0 = *reinterpret_cast<const float4*>(bias + o4);
    const float4 bv1 = *reinterpret_cast<const float4*>(bias + 768 + o4);
    const float4 bv2 = *reinterpret_cast<const float4*>(bias + 1536 + o4);
    const float4 bv3 = *reinterpret_cast<const float4*>(bias + 2304 + o4);
    *reinterpret_cast<float4*>(ob) =
        make_float4(r0[0]+bv0.x, r0[1]+bv0.y, r0[2]+bv0.z, r0[3]+bv0.w);
    *reinterpret_cast<float4*>(ob + 768) =
        make_float4(r1[0]+bv1.x, r1[1]+bv1.y, r1[2]+bv1.z, r1[3]+bv1.w);
    *reinterpret_cast<float4*>(ob + 1536) =
        make_float4(r2[0]+bv2.x, r2[1]+bv2.y, r2[2]+bv2.z, r2[3]+bv2.w);
    *reinterpret_cast<float4*>(ob + 2304) =
        make_float4(r3[0]+bv3.x, r3[1]+bv3.y, r3[2]+bv3.z, r3[3]+bv3.w);
}

// ---------------------------------------------------------------------------
extern "C" void kernel_launch(void* const* d_in, const int* in_sizes, int n_in,
                              void* d_out, int out_size) {
    const float* x    = (const float*)d_in[0];
    const float* w    = (const float*)d_in[1];
    const float* bias = (const float*)d_in[2];
    float* out = (float*)d_out;

    cudaFuncSetAttribute(gemm_f16_kernel,
                         cudaFuncAttributeMaxDynamicSharedMemorySize, SMEM_BYTES);

    prep_xt_kernel<<<(M_DIM * 24) / 128, 128>>>(x);     // 1176 blocks
    prep_bp_kernel<<<13824 / 128, 128>>>(w);            // 108 blocks

    dim3 grid(24, 49);
    gemm_f16_kernel<<<grid, 256, SMEM_BYTES>>>();

    combine_kernel<<<(M_DIM * 192) / 256, 256>>>(bias, out);  // 4704 blocks
}